// round 7
// baseline (speedup 1.0000x reference)
#include <cuda_runtime.h>
#include <math.h>
#include <stdint.h>

// Biquad lowpass (fs=44100, fc=10000, Q=0.707) as truncated-FIR (K=12,
// pole mag 0.4203 -> trunc err ~3.8e-5 << 1e-3).
// R6b: cp.async double-buffered pipeline (R6 + missing stdint include).
// Block walks 9 tiles of 2048 outputs along a strip; tile i+1 streams into
// buf^1 via LDGSTS while tile i is computed from buf (conflict-free LDS.128
// windows, 16B lane stride). Grid 9x128 = 1152 blocks = one wave at 8/SM.

#define K_TAPS   12
#define T_LEN    160000
#define THREADS  256
#define TILE     2048
#define HALO     16
#define BUF_F    (TILE + HALO)          // 2064 floats
#define BUF_V4   (BUF_F / 4)            // 516 float4
#define BLOCKS_X 9
#define SPB      17792                  // strip per block (multiple of 16)
#define NT       ((SPB + TILE - 1) / TILE)  // 9 tiles

struct FirParams {
    float h[K_TAPS];
};

__device__ __forceinline__ void cp_async16(unsigned int saddr, const float* g, int src_bytes) {
    asm volatile("cp.async.ca.shared.global [%0], [%1], 16, %2;\n"
                 :: "r"(saddr), "l"(g), "r"(src_bytes) : "memory");
}

__global__ __launch_bounds__(THREADS) void lowpass_fir_kernel(
    const float* __restrict__ clip,
    float* __restrict__ out,
    FirParams p)
{
    __shared__ alignas(16) float buf[2][BUF_F];

    const int tid = threadIdx.x;
    const size_t row = (size_t)blockIdx.y * T_LEN;
    const float* __restrict__ x = clip + row;
    float* __restrict__ o = out + row;

    const int strip0 = blockIdx.x * SPB;
    const int strip_end = min(strip0 + SPB, T_LEN);

    // Issue async copy of one tile (g = first output index) into buf[bi].
    auto issue_tile = [&](int tile_idx, int bi) {
        const int g = strip0 + tile_idx * TILE;
        const unsigned int sbase = (unsigned int)__cvta_generic_to_shared(&buf[bi][0]);
        #pragma unroll
        for (int k = 0; k < (BUF_V4 + THREADS - 1) / THREADS; k++) {
            const int v = k * THREADS + tid;
            if (v < BUF_V4) {
                const int base = g - HALO + 4 * v;    // multiple of 4
                const bool valid = (base >= 0) && (base <= T_LEN - 4);
                const float* gp = valid ? (x + base) : x;   // keep ptr legal
                cp_async16(sbase + 16u * (unsigned int)v, gp, valid ? 16 : 0);
            }
        }
        asm volatile("cp.async.commit_group;\n" ::: "memory");
    };

    issue_tile(0, 0);
    int cur = 0;

    for (int i = 0; i < NT; i++) {
        if (i + 1 < NT) {
            issue_tile(i + 1, cur ^ 1);   // prefetch next tile into other buffer
            asm volatile("cp.async.wait_group 1;\n" ::: "memory");  // tile i done
        } else {
            asm volatile("cp.async.wait_group 0;\n" ::: "memory");
        }
        __syncthreads();   // all threads' copies for tile i visible

        const int g = strip0 + i * TILE;
        const float* __restrict__ sm = buf[cur];

        #pragma unroll
        for (int sub = 0; sub < TILE / (THREADS * 4); sub++) {
            const int ofs = sub * (THREADS * 4) + tid * 4;  // local output index
            const int t = g + ofs;
            if (t < strip_end) {
                // Window w[j] = x[t - 12 + j] = sm[ofs + 4 + j], j = 0..15.
                // ofs + 4 multiple of 4, lane stride 16B -> conflict-free LDS.128.
                const float4* __restrict__ w4 =
                    reinterpret_cast<const float4*>(sm + ofs + 4);
                float w[16];
                #pragma unroll
                for (int j = 0; j < 4; j++) {
                    float4 v = w4[j];
                    w[4 * j + 0] = v.x;
                    w[4 * j + 1] = v.y;
                    w[4 * j + 2] = v.z;
                    w[4 * j + 3] = v.w;
                }

                float y0 = 0.f, y1 = 0.f, y2 = 0.f, y3 = 0.f;
                #pragma unroll
                for (int k = 0; k < K_TAPS; k++) {
                    const float hk = p.h[k];
                    y0 = fmaf(hk, w[12 + 0 - k], y0);
                    y1 = fmaf(hk, w[12 + 1 - k], y1);
                    y2 = fmaf(hk, w[12 + 2 - k], y2);
                    y3 = fmaf(hk, w[12 + 3 - k], y3);
                }

                float4 r;
                r.x = y0; r.y = y1; r.z = y2; r.w = y3;
                *reinterpret_cast<float4*>(o + t) = r;   // coalesced store
            }
        }
        __syncthreads();   // protect buf[cur] WAR before it becomes prefetch dst
        cur ^= 1;
    }
}

extern "C" void kernel_launch(void* const* d_in, const int* in_sizes, int n_in,
                              void* d_out, int out_size)
{
    const float* clip = (const float*)d_in[0];
    float* out = (float*)d_out;

    const int total = in_sizes[0];
    const int batch = total / T_LEN;   // 128

    // Coefficients in double, exactly as the reference computes them.
    const double fs = 44100.0, fc = 10000.0, q = 0.707;
    const double w0 = 2.0 * M_PI * fc / fs;
    const double alpha = sin(w0) / (2.0 * q);
    const double cw = cos(w0);
    const double a0 = 1.0 + alpha;
    const double b0 = ((1.0 - cw) / 2.0) / a0;
    const double b1 = (1.0 - cw) / a0;
    const double b2 = b0;
    const double a1 = (-2.0 * cw) / a0;
    const double a2 = (1.0 - alpha) / a0;

    // Impulse response of the biquad (truncated to K_TAPS).
    double hd[K_TAPS];
    hd[0] = b0;
    hd[1] = b1 - a1 * hd[0];
    hd[2] = b2 - a1 * hd[1] - a2 * hd[0];
    for (int k = 3; k < K_TAPS; k++)
        hd[k] = -a1 * hd[k - 1] - a2 * hd[k - 2];

    FirParams p;
    for (int k = 0; k < K_TAPS; k++) p.h[k] = (float)hd[k];

    dim3 grid(BLOCKS_X, batch);   // 9 x 128 = 1152 blocks, one wave @ 8/SM
    lowpass_fir_kernel<<<grid, THREADS>>>(clip, out, p);
}

// round 8
// speedup vs baseline: 1.0072x; 1.0072x over previous
#include <cuda_runtime.h>
#include <math.h>
#include <stdint.h>

// Biquad lowpass (fs=44100, fc=10000, Q=0.707) as truncated-FIR (K=12,
// pole mag 0.4203 -> trunc err ~3.8e-5 << 1e-3).
// R8: 4-stage cp.async pipeline, TILE=1024, 3 tiles in flight (wait_group 2),
// cp.async.cg to bypass L1 for the stream-once input. Conflict-free LDS.128
// windows (16B lane stride). Grid 9x128 = one wave at 8 blocks/SM.

#define K_TAPS   12
#define T_LEN    160000
#define THREADS  256
#define TILE     1024
#define HALO     16
#define BUF_F    (TILE + HALO)          // 1040 floats
#define BUF_V4   (BUF_F / 4)            // 260 float4
#define STAGES   4
#define BLOCKS_X 9
#define NT       18                     // tiles per block
#define SPB      (NT * TILE)            // 18432

struct FirParams {
    float h[K_TAPS];
};

__device__ __forceinline__ void cp_async16_cg(unsigned int saddr, const float* g, int src_bytes) {
    asm volatile("cp.async.cg.shared.global [%0], [%1], 16, %2;\n"
                 :: "r"(saddr), "l"(g), "r"(src_bytes) : "memory");
}

__global__ __launch_bounds__(THREADS) void lowpass_fir_kernel(
    const float* __restrict__ clip,
    float* __restrict__ out,
    FirParams p)
{
    __shared__ alignas(16) float buf[STAGES][BUF_F];

    const int tid = threadIdx.x;
    const size_t row = (size_t)blockIdx.y * T_LEN;
    const float* __restrict__ x = clip + row;
    float* __restrict__ o = out + row;

    const int strip0 = blockIdx.x * SPB;

    // Issue async copy of tile `tile_idx` into buf[tile_idx % STAGES].
    auto issue_tile = [&](int tile_idx) {
        const int g = strip0 + tile_idx * TILE;
        const unsigned int sbase =
            (unsigned int)__cvta_generic_to_shared(&buf[tile_idx & (STAGES - 1)][0]);
        #pragma unroll
        for (int k = 0; k < (BUF_V4 + THREADS - 1) / THREADS; k++) {
            const int v = k * THREADS + tid;
            if (v < BUF_V4) {
                const int base = g - HALO + 4 * v;    // multiple of 4
                const bool valid = (base >= 0) && (base <= T_LEN - 4);
                const float* gp = valid ? (x + base) : x;   // keep ptr legal
                cp_async16_cg(sbase + 16u * (unsigned int)v, gp, valid ? 16 : 0);
            }
        }
        asm volatile("cp.async.commit_group;\n" ::: "memory");
    };

    // Prologue: fill 3 of the 4 stages.
    issue_tile(0);
    issue_tile(1);
    issue_tile(2);

    for (int i = 0; i < NT; i++) {
        if (i + 3 < NT) {
            // Tiles issued so far: 0..i+2. Allow 2 pending -> tile i complete.
            asm volatile("cp.async.wait_group 2;\n" ::: "memory");
        } else {
            asm volatile("cp.async.wait_group %0;\n" :: "n"(0) : "memory");
            // (tail: just drain everything; cheap, only last 3 iterations)
        }
        __syncthreads();   // tile i visible to all; compute(i-1) done -> buf[(i+3)%4] free

        if (i + 3 < NT) issue_tile(i + 3);

        const int g = strip0 + i * TILE;
        const float* __restrict__ sm = buf[i & (STAGES - 1)];

        const int ofs = tid * 4;           // local output index (TILE = THREADS*4)
        const int t = g + ofs;
        if (t < T_LEN) {
            // Window w[j] = x[t - 12 + j] = sm[ofs + 4 + j], j = 0..15.
            // ofs + 4 multiple of 4, 16B lane stride -> conflict-free LDS.128.
            const float4* __restrict__ w4 =
                reinterpret_cast<const float4*>(sm + ofs + 4);
            float w[16];
            #pragma unroll
            for (int j = 0; j < 4; j++) {
                float4 v = w4[j];
                w[4 * j + 0] = v.x;
                w[4 * j + 1] = v.y;
                w[4 * j + 2] = v.z;
                w[4 * j + 3] = v.w;
            }

            float y0 = 0.f, y1 = 0.f, y2 = 0.f, y3 = 0.f;
            #pragma unroll
            for (int k = 0; k < K_TAPS; k++) {
                const float hk = p.h[k];
                y0 = fmaf(hk, w[12 + 0 - k], y0);
                y1 = fmaf(hk, w[12 + 1 - k], y1);
                y2 = fmaf(hk, w[12 + 2 - k], y2);
                y3 = fmaf(hk, w[12 + 3 - k], y3);
            }

            float4 r;
            r.x = y0; r.y = y1; r.z = y2; r.w = y3;
            *reinterpret_cast<float4*>(o + t) = r;   // coalesced store
        }
        __syncthreads();   // all reads of buf[i%4] done before it is refilled
    }
}

extern "C" void kernel_launch(void* const* d_in, const int* in_sizes, int n_in,
                              void* d_out, int out_size)
{
    const float* clip = (const float*)d_in[0];
    float* out = (float*)d_out;

    const int total = in_sizes[0];
    const int batch = total / T_LEN;   // 128

    // Coefficients in double, exactly as the reference computes them.
    const double fs = 44100.0, fc = 10000.0, q = 0.707;
    const double w0 = 2.0 * M_PI * fc / fs;
    const double alpha = sin(w0) / (2.0 * q);
    const double cw = cos(w0);
    const double a0 = 1.0 + alpha;
    const double b0 = ((1.0 - cw) / 2.0) / a0;
    const double b1 = (1.0 - cw) / a0;
    const double b2 = b0;
    const double a1 = (-2.0 * cw) / a0;
    const double a2 = (1.0 - alpha) / a0;

    // Impulse response of the biquad (truncated to K_TAPS).
    double hd[K_TAPS];
    hd[0] = b0;
    hd[1] = b1 - a1 * hd[0];
    hd[2] = b2 - a1 * hd[1] - a2 * hd[0];
    for (int k = 3; k < K_TAPS; k++)
        hd[k] = -a1 * hd[k - 1] - a2 * hd[k - 2];

    FirParams p;
    for (int k = 0; k < K_TAPS; k++) p.h[k] = (float)hd[k];

    dim3 grid(BLOCKS_X, batch);   // 9 x 128 = 1152 blocks, one wave @ 8/SM
    lowpass_fir_kernel<<<grid, THREADS>>>(clip, out, p);
}